// round 5
// baseline (speedup 1.0000x reference)
#include <cuda_runtime.h>
#include <math.h>

// NTM shapes
#define Bb 256
#define Tt 128
#define Ii 512
#define Hh 512
#define Nn 1024
#define Mm 512
#define Oo 512
#define NBLK 148
#define NTHR 512
#define BH (Bb * Hh)
#define BM (Bb * Mm)

// ---------------- persistent state / scratch (device globals) ---------------
__device__ float g_mem[Nn * Mm];
__device__ float g_wr[Bb * Nn];
__device__ float g_ww[Bb * Nn];
__device__ float g_h[Bb * Hh];
__device__ float g_ea[Bb * 2 * Mm];
__device__ float g_rpart[4 * Bb * Mm];
__device__ float g_hpart[4 * Bb * Hh];
__device__ float g_pw[Bb * (Mm + 6)];
__device__ float g_pr[Bb * (Mm + 6)];
__device__ float g_scw[Bb * 8];
__device__ float g_scr[Bb * 8];
__device__ float g_simw[Bb * Nn];
__device__ float g_simr[Bb * Nn];
__device__ float g_invmem[Nn];
__device__ unsigned g_bar_count;
__device__ unsigned g_bar_gen;

// ---------------- grid barrier ----------------------------------------------
static __device__ __forceinline__ void gridBarrier() {
    __syncthreads();
    __threadfence();
    if (threadIdx.x == 0) {
        unsigned gen = *(volatile unsigned*)&g_bar_gen;
        unsigned prev = atomicAdd(&g_bar_count, 1u);
        if (prev == NBLK - 1) {
            g_bar_count = 0;
            __threadfence();
            *(volatile unsigned*)&g_bar_gen = gen + 1;
        } else {
            while (*(volatile unsigned*)&g_bar_gen == gen) { __nanosleep(64); }
        }
    }
    __syncthreads();
}

// ---------------- math helpers ----------------------------------------------
static __device__ __forceinline__ float sigm(float x) { return 1.f / (1.f + __expf(-x)); }
static __device__ __forceinline__ float tanh_f(float x) {
    float t = __expf(-2.f * fabsf(x));
    float r = (1.f - t) / (1.f + t);
    return copysignf(r, x);
}
static __device__ __forceinline__ float softplus_(float x) {
    return fmaxf(x, 0.f) + log1pf(__expf(-fabsf(x)));
}
static __device__ __forceinline__ float warpReduceSum(float v) {
    #pragma unroll
    for (int o = 16; o > 0; o >>= 1) v += __shfl_xor_sync(0xffffffffu, v, o);
    return v;
}
static __device__ __forceinline__ float warpReduceMax(float v) {
    #pragma unroll
    for (int o = 16; o > 0; o >>= 1) v = fmaxf(v, __shfl_xor_sync(0xffffffffu, v, o));
    return v;
}
static __device__ __forceinline__ float blockReduceSum512(float v) {
    __shared__ float sh[16];
    int lane = threadIdx.x & 31, wid = threadIdx.x >> 5;
    v = warpReduceSum(v);
    if (lane == 0) sh[wid] = v;
    __syncthreads();
    if (wid == 0) {
        float t = (lane < 16) ? sh[lane] : 0.f;
        t = warpReduceSum(t);
        if (lane == 0) sh[0] = t;
    }
    __syncthreads();
    float r = sh[0];
    __syncthreads();
    return r;
}
static __device__ __forceinline__ float blockReduceMax512(float v) {
    __shared__ float sh[16];
    int lane = threadIdx.x & 31, wid = threadIdx.x >> 5;
    v = warpReduceMax(v);
    if (lane == 0) sh[wid] = v;
    __syncthreads();
    if (wid == 0) {
        float t = (lane < 16) ? sh[lane] : -3.4e38f;
        t = warpReduceMax(t);
        if (lane == 0) sh[0] = t;
    }
    __syncthreads();
    float r = sh[0];
    __syncthreads();
    return r;
}

// acc[8] += a * w8
#define FMA1x8(acc, a, w0, w1)                 \
    {                                          \
        acc[0] = fmaf(a, w0.x, acc[0]);        \
        acc[1] = fmaf(a, w0.y, acc[1]);        \
        acc[2] = fmaf(a, w0.z, acc[2]);        \
        acc[3] = fmaf(a, w0.w, acc[3]);        \
        acc[4] = fmaf(a, w1.x, acc[4]);        \
        acc[5] = fmaf(a, w1.y, acc[5]);        \
        acc[6] = fmaf(a, w1.z, acc[6]);        \
        acc[7] = fmaf(a, w1.w, acc[7]);        \
    }

// ---------------- 64x64 NN GEMM tile, 512 thr, 1x8 micro, double-buffered ---
// C = act(A@W + bias).  act: 0 none, 2 sigmoid, 3 tanh col<512, 4 sig|tanh.
// compute map: ty = tid>>3 (row 0..63), tx = tid&7 (8 cols each)
static __device__ __forceinline__ void gemm64_nn(
    const float* __restrict__ A, int lda,
    const float* __restrict__ W, int ldw,
    const float* __restrict__ bias,
    float* __restrict__ C, int ldc,
    int bm, int bn, int Nc, int K, int act, float* shb)
{
    float (*As)[16][68] = (float(*)[16][68])shb;              // 2*1088
    float (*Ws)[16][64] = (float(*)[16][64])(shb + 2176);     // 2*1024
    const int tid = threadIdx.x;
    const int tx = tid & 7, ty = tid >> 3;
    const int am = tid >> 3, ak = tid & 7;      // A staging: row am, k = ak, ak+8
    const int wk = tid >> 5, wn = tid & 31;     // W staging: k = wk, col = wn, wn+32
    const float* Aptr = A + (size_t)(bm + am) * lda + ak;
    const float* Wptr = W + (size_t)wk * ldw + bn + wn;
    const bool wok0 = (bn + wn) < Nc, wok1 = (bn + wn + 32) < Nc;

    float acc[8] = {};
    float ra0 = Aptr[0], ra1 = Aptr[8];
    float rw0 = wok0 ? Wptr[0] : 0.f;
    float rw1 = wok1 ? Wptr[32] : 0.f;
    As[0][ak][am] = ra0; As[0][ak + 8][am] = ra1;
    Ws[0][wk][wn] = rw0; Ws[0][wk][wn + 32] = rw1;
    __syncthreads();
    int buf = 0;
    for (int k0 = 0; k0 < K; k0 += 16) {
        if (k0 + 16 < K) {
            ra0 = Aptr[k0 + 16];
            ra1 = Aptr[k0 + 24];
            const float* Wp = Wptr + (size_t)(k0 + 16) * ldw;
            rw0 = wok0 ? Wp[0] : 0.f;
            rw1 = wok1 ? Wp[32] : 0.f;
        }
        #pragma unroll
        for (int kk = 0; kk < 16; kk++) {
            float a = As[buf][kk][ty];
            float4 w0 = *(const float4*)&Ws[buf][kk][tx * 8];
            float4 w1 = *(const float4*)&Ws[buf][kk][tx * 8 + 4];
            FMA1x8(acc, a, w0, w1);
        }
        if (k0 + 16 < K) {
            __syncthreads();
            As[buf ^ 1][ak][am] = ra0; As[buf ^ 1][ak + 8][am] = ra1;
            Ws[buf ^ 1][wk][wn] = rw0; Ws[buf ^ 1][wk][wn + 32] = rw1;
            __syncthreads();
            buf ^= 1;
        }
    }
    __syncthreads();
    int row = bm + ty;
    #pragma unroll
    for (int j = 0; j < 8; j++) {
        int col = bn + tx * 8 + j;
        if (col >= Nc) continue;
        float v = acc[j];
        if (bias) v += bias[col];
        if (act == 2) v = sigm(v);
        else if (act == 3) { if (col < 512) v = tanh_f(v); }
        else if (act == 4) { v = (col < 512) ? sigm(v) : tanh_f(v); }
        C[(size_t)row * ldc + col] = v;
    }
}

// ---------------- 64x64 NT GEMM tile: C[b,n] = sum_k A[b,k]*Bm[n,k] ---------
static __device__ __forceinline__ void gemm64_nt(
    const float* __restrict__ A, int lda,
    const float* __restrict__ Bm, int ldb,
    float* __restrict__ C, int ldc,
    int bm, int bn, int K, float* shb)
{
    float (*As)[16][68] = (float(*)[16][68])shb;
    float (*Bs)[16][68] = (float(*)[16][68])(shb + 2176);
    const int tid = threadIdx.x;
    const int tx = tid & 7, ty = tid >> 3;
    const int am = tid >> 3, ak = tid & 7;
    const float* Aptr = A + (size_t)(bm + am) * lda + ak;
    const float* Bptr = Bm + (size_t)(bn + am) * ldb + ak;

    float acc[8] = {};
    float ra0 = Aptr[0], ra1 = Aptr[8];
    float rb0 = Bptr[0], rb1 = Bptr[8];
    As[0][ak][am] = ra0; As[0][ak + 8][am] = ra1;
    Bs[0][ak][am] = rb0; Bs[0][ak + 8][am] = rb1;
    __syncthreads();
    int buf = 0;
    for (int k0 = 0; k0 < K; k0 += 16) {
        if (k0 + 16 < K) {
            ra0 = Aptr[k0 + 16];
            ra1 = Aptr[k0 + 24];
            rb0 = Bptr[k0 + 16];
            rb1 = Bptr[k0 + 24];
        }
        #pragma unroll
        for (int kk = 0; kk < 16; kk++) {
            float a = As[buf][kk][ty];
            float4 w0 = *(const float4*)&Bs[buf][kk][tx * 8];
            float4 w1 = *(const float4*)&Bs[buf][kk][tx * 8 + 4];
            FMA1x8(acc, a, w0, w1);
        }
        if (k0 + 16 < K) {
            __syncthreads();
            As[buf ^ 1][ak][am] = ra0; As[buf ^ 1][ak + 8][am] = ra1;
            Bs[buf ^ 1][ak][am] = rb0; Bs[buf ^ 1][ak + 8][am] = rb1;
            __syncthreads();
            buf ^= 1;
        }
    }
    __syncthreads();
    int row = bm + ty;
    #pragma unroll
    for (int j = 0; j < 8; j++)
        C[(size_t)row * ldc + (bn + tx * 8 + j)] = acc[j];
}

// ---------------- mem update tile: mem = mem*(1 - ww^T e/B) + ww^T a/B ------
// tile: 64 n-rows x 64 m-cols, K = Bb = 256 batch
static __device__ __forceinline__ void memupd_tile(int tn, int tm, float* shb)
{
    float (*Wws)[16][68] = (float(*)[16][68])shb;             // [b][n]
    float (*Es)[16][64]  = (float(*)[16][64])(shb + 2176);    // [b][m]
    float (*Aas)[16][64] = (float(*)[16][64])(shb + 2176 + 2048);
    const int bnrow = tn * 64, bmcol = tm * 64;
    const int tid = threadIdx.x;
    const int tx = tid & 7, ty = tid >> 3;
    const int lk = tid >> 5, ln = tid & 31;     // staging: b = lk, idx = ln, ln+32
    const float* wp = g_ww + (size_t)lk * Nn + bnrow + ln;
    const float* ep = g_ea + (size_t)lk * (2 * Mm) + bmcol + ln;
    const float* ap = ep + Mm;

    float acce[8] = {};
    float acca[8] = {};
    float rw0 = wp[0], rw1 = wp[32];
    float re0 = ep[0], re1 = ep[32];
    float rr0 = ap[0], rr1 = ap[32];
    Wws[0][lk][ln] = rw0; Wws[0][lk][ln + 32] = rw1;
    Es[0][lk][ln]  = re0; Es[0][lk][ln + 32]  = re1;
    Aas[0][lk][ln] = rr0; Aas[0][lk][ln + 32] = rr1;
    __syncthreads();
    int buf = 0;
    for (int b0 = 0; b0 < Bb; b0 += 16) {
        if (b0 + 16 < Bb) {
            const float* wp2 = wp + (size_t)(b0 + 16) * Nn;
            const float* ep2 = ep + (size_t)(b0 + 16) * (2 * Mm);
            const float* ap2 = ap + (size_t)(b0 + 16) * (2 * Mm);
            rw0 = wp2[0]; rw1 = wp2[32];
            re0 = ep2[0]; re1 = ep2[32];
            rr0 = ap2[0]; rr1 = ap2[32];
        }
        #pragma unroll
        for (int kk = 0; kk < 16; kk++) {
            float w = Wws[buf][kk][ty];
            float4 e0 = *(const float4*)&Es[buf][kk][tx * 8];
            float4 e1 = *(const float4*)&Es[buf][kk][tx * 8 + 4];
            float4 a0 = *(const float4*)&Aas[buf][kk][tx * 8];
            float4 a1 = *(const float4*)&Aas[buf][kk][tx * 8 + 4];
            FMA1x8(acce, w, e0, e1);
            FMA1x8(acca, w, a0, a1);
        }
        if (b0 + 16 < Bb) {
            __syncthreads();
            Wws[buf ^ 1][lk][ln] = rw0; Wws[buf ^ 1][lk][ln + 32] = rw1;
            Es[buf ^ 1][lk][ln]  = re0; Es[buf ^ 1][lk][ln + 32]  = re1;
            Aas[buf ^ 1][lk][ln] = rr0; Aas[buf ^ 1][lk][ln + 32] = rr1;
            __syncthreads();
            buf ^= 1;
        }
    }
    __syncthreads();
    const float invB = 1.f / (float)Bb;
    int n = bnrow + ty;
    #pragma unroll
    for (int j = 0; j < 8; j++) {
        int m = bmcol + tx * 8 + j;
        float old = g_mem[(size_t)n * Mm + m];
        g_mem[(size_t)n * Mm + m] = old * (1.f - acce[j] * invB) + acca[j] * invB;
    }
}

// ---------------- controller split-K tile ------------------------------------
// chunk c: 0,1 -> x halves; 2,3 -> r (= sum of 4 rpart) halves. K=256 each.
static __device__ __forceinline__ void gemmD_tile(
    int c, int bm, int bn, const float* __restrict__ xb,
    const float* __restrict__ Wx, const float* __restrict__ Wr, float* shb)
{
    float (*As)[16][68] = (float(*)[16][68])shb;
    float (*Ws)[16][64] = (float(*)[16][64])(shb + 2176);
    const int tid = threadIdx.x;
    const int tx = tid & 7, ty = tid >> 3;
    const int am = tid >> 3, ak = tid & 7;
    const int wk = tid >> 5, wn = tid & 31;
    const float* Wptr = ((c < 2) ? (Wx + (size_t)c * 256 * Hh)
                                 : (Wr + (size_t)(c - 2) * 256 * Hh))
                        + (size_t)wk * Hh + bn + wn;
    const float* Ax = xb + (size_t)(bm + am) * (Tt * Ii) + c * 256 + ak;
    const float* Ar = g_rpart + (size_t)(bm + am) * Mm + (c - 2) * 256 + ak;

    float acc[8] = {};
    float ra0, ra1;
    if (c < 2) { ra0 = Ax[0]; ra1 = Ax[8]; }
    else {
        const float* p0 = Ar;
        const float* p1 = Ar + 8;
        ra0 = p0[0] + p0[BM] + p0[2 * BM] + p0[3 * BM];
        ra1 = p1[0] + p1[BM] + p1[2 * BM] + p1[3 * BM];
    }
    float rw0 = Wptr[0], rw1 = Wptr[32];
    As[0][ak][am] = ra0; As[0][ak + 8][am] = ra1;
    Ws[0][wk][wn] = rw0; Ws[0][wk][wn + 32] = rw1;
    __syncthreads();
    int buf = 0;
    for (int k0 = 0; k0 < 256; k0 += 16) {
        if (k0 + 16 < 256) {
            if (c < 2) { ra0 = Ax[k0 + 16]; ra1 = Ax[k0 + 24]; }
            else {
                const float* p0 = Ar + k0 + 16;
                const float* p1 = Ar + k0 + 24;
                ra0 = p0[0] + p0[BM] + p0[2 * BM] + p0[3 * BM];
                ra1 = p1[0] + p1[BM] + p1[2 * BM] + p1[3 * BM];
            }
            const float* Wp = Wptr + (size_t)(k0 + 16) * Hh;
            rw0 = Wp[0]; rw1 = Wp[32];
        }
        #pragma unroll
        for (int kk = 0; kk < 16; kk++) {
            float a = As[buf][kk][ty];
            float4 w0 = *(const float4*)&Ws[buf][kk][tx * 8];
            float4 w1 = *(const float4*)&Ws[buf][kk][tx * 8 + 4];
            FMA1x8(acc, a, w0, w1);
        }
        if (k0 + 16 < 256) {
            __syncthreads();
            As[buf ^ 1][ak][am] = ra0; As[buf ^ 1][ak + 8][am] = ra1;
            Ws[buf ^ 1][wk][wn] = rw0; Ws[buf ^ 1][wk][wn + 32] = rw1;
            __syncthreads();
            buf ^= 1;
        }
    }
    __syncthreads();
    float* C = g_hpart + (size_t)c * BH;
    int row = bm + ty;
    #pragma unroll
    for (int j = 0; j < 8; j++)
        C[(size_t)row * Hh + (bn + tx * 8 + j)] = acc[j];
}

// ---------------- small row-wise items ---------------------------------------
static __device__ __noinline__ void invnorm_item(int item)
{
    int w = threadIdx.x >> 5, lane = threadIdx.x & 31;
    for (int rr = w; rr < 128; rr += 16) {
        int n = item * 128 + rr;
        float s = 0.f;
        for (int c = lane; c < Mm; c += 32) {
            float v = g_mem[(size_t)n * Mm + c];
            s += v * v;
        }
        s = warpReduceSum(s);
        if (lane == 0) g_invmem[n] = 1.f / (sqrtf(s) + 1e-8f);
    }
}

static __device__ __noinline__ void scalars_item(int i)
{
    int head = i >> 3, rb = i & 7;
    const float* p = head ? g_pr : g_pw;
    float* sc = head ? g_scr : g_scw;
    int w = threadIdx.x >> 5, lane = threadIdx.x & 31;
    for (int rr = w; rr < 32; rr += 16) {
        int b = rb * 32 + rr;
        const float* row = p + (size_t)b * (Mm + 6);
        float s = 0.f;
        for (int c = lane; c < Mm; c += 32) {
            float v = row[c];
            s += v * v;
        }
        s = warpReduceSum(s);
        if (lane == 0) {
            sc[b * 8 + 0] = softplus_(row[Mm + 0]);
            sc[b * 8 + 1] = sigm(row[Mm + 1]);
            float s0 = row[Mm + 2], s1 = row[Mm + 3], s2 = row[Mm + 4];
            float mx = fmaxf(s0, fmaxf(s1, s2));
            float e0 = __expf(s0 - mx), e1 = __expf(s1 - mx), e2 = __expf(s2 - mx);
            float inv = 1.f / (e0 + e1 + e2);
            sc[b * 8 + 2] = e0 * inv;
            sc[b * 8 + 3] = e1 * inv;
            sc[b * 8 + 4] = e2 * inv;
            sc[b * 8 + 5] = 1.f + softplus_(row[Mm + 5]);
            sc[b * 8 + 6] = 1.f / (sqrtf(s) + 1e-8f);
        }
    }
}

// -------- fused address tail: softmax -> interpolate -> shift -> sharpen -----
static __device__ __noinline__ void tail_item(int it, float* shb)
{
    float* wg = shb;                  // 1024 floats
    int b = it & 255, head = it >> 8;
    const float* sim = head ? g_simr : g_simw;
    float* wv = head ? g_wr : g_ww;
    const float* sc = head ? g_scr : g_scw;
    int tid = threadIdx.x;
    float beta = sc[b * 8 + 0], g = sc[b * 8 + 1];
    float s0 = sc[b * 8 + 2], s1 = sc[b * 8 + 3], s2 = sc[b * 8 + 4];
    float gamma = sc[b * 8 + 5], invk = sc[b * 8 + 6];
    float scale = beta * invk;

    float v[2];
    float mx = -3.4e38f;
    #pragma unroll
    for (int i = 0; i < 2; i++) {
        int n = tid + i * 512;
        float t = sim[(size_t)b * Nn + n] * scale * g_invmem[n];
        v[i] = t;
        mx = fmaxf(mx, t);
    }
    mx = blockReduceMax512(mx);
    float s = 0.f;
    #pragma unroll
    for (int i = 0; i < 2; i++) { v[i] = __expf(v[i] - mx); s += v[i]; }
    s = blockReduceSum512(s);
    float invs = 1.f / s;
    #pragma unroll
    for (int i = 0; i < 2; i++) {
        int n = tid + i * 512;
        wg[n] = g * (v[i] * invs) + (1.f - g) * wv[(size_t)b * Nn + n];
    }
    __syncthreads();
    float wp[2];
    float local = 0.f;
    #pragma unroll
    for (int i = 0; i < 2; i++) {
        int n = tid + i * 512;
        float wt = s0 * wg[(n + 1) & (Nn - 1)] + s1 * wg[n] + s2 * wg[(n - 1) & (Nn - 1)];
        float pv = __powf(wt, gamma);
        wp[i] = pv;
        local += pv;
    }
    local = blockReduceSum512(local);
    float invt = 1.f / (local + 1e-8f);
    #pragma unroll
    for (int i = 0; i < 2; i++) {
        int n = tid + i * 512;
        wv[(size_t)b * Nn + n] = wp[i] * invt;
    }
    __syncthreads();
}

// ---------------- the persistent kernel --------------------------------------
__global__ void __launch_bounds__(NTHR, 1) ntm_persistent(
    const float* __restrict__ x,
    const float* __restrict__ mem0, const float* __restrict__ wr0,
    const float* __restrict__ ww0,  const float* __restrict__ h0,
    const float* __restrict__ Wx,   const float* __restrict__ Wr,
    const float* __restrict__ bh,
    const float* __restrict__ Whr,  const float* __restrict__ bhr,
    const float* __restrict__ Whw,  const float* __restrict__ bhw,
    const float* __restrict__ Wea,  const float* __restrict__ bea,
    const float* __restrict__ Wo,   const float* __restrict__ bo,
    float* __restrict__ out)
{
    // max user: memupd 2176 + 2048 + 2048 = 6272 floats = 25.1 KB
    __shared__ __align__(16) float shbuf[6272];
    const int tid = threadIdx.x;
    const int gtid = blockIdx.x * NTHR + tid;
    const int gstride = NBLK * NTHR;

    // P0: init carried state
    for (int i = gtid; i < Nn * Mm; i += gstride) g_mem[i] = mem0[i];
    for (int i = gtid; i < Bb * Nn; i += gstride) { g_wr[i] = wr0[i]; g_ww[i] = ww0[i]; }
    for (int i = gtid; i < Bb * Hh; i += gstride) g_h[i] = h0[i];
    gridBarrier();

    // P1: ea from h0 (64 tiles)
    for (int it = blockIdx.x; it < 64; it += NBLK) {
        int tm = it >> 4, tn = it & 15;
        gemm64_nn(g_h, Hh, Wea, 2 * Mm, bea, g_ea, 2 * Mm,
                  tm * 64, tn * 64, 2 * Mm, Hh, 4, shbuf);
    }
    gridBarrier();

    for (int t = 0; t < Tt; t++) {
        // B: memupd (128) + out_{t-1} tiles 0..19  => exactly 148 items
        for (int it = blockIdx.x; it < 148; it += NBLK) {
            if (it < 128) memupd_tile(it >> 3, it & 7, shbuf);
            else if (t > 0) {
                int o = it - 128;                         // 0..19
                gemm64_nn(g_h, Hh, Wo, Oo, bo, out + (size_t)(t - 1) * Oo, Tt * Oo,
                          (o >> 3) * 64, (o & 7) * 64, Oo, Hh, 2, shbuf);
            }
        }
        gridBarrier();

        // C: r split-K (128) + invnorm (8) + out_{t-1} tiles 20..31 => 148
        for (int it = blockIdx.x; it < 148; it += NBLK) {
            if (it < 128) {
                int c = it >> 5, rest = it & 31, tm = rest >> 3, tn = rest & 7;
                gemm64_nn(g_wr + c * 256, Nn, g_mem + (size_t)c * 256 * Mm, Mm, nullptr,
                          g_rpart + (size_t)c * BM, Mm, tm * 64, tn * 64, Mm, 256, 0, shbuf);
            } else if (it < 136) invnorm_item(it - 128);
            else if (t > 0) {
                int o = it - 136 + 20;                    // 20..31
                gemm64_nn(g_h, Hh, Wo, Oo, bo, out + (size_t)(t - 1) * Oo, Tt * Oo,
                          (o >> 3) * 64, (o & 7) * 64, Oo, Hh, 2, shbuf);
            }
        }
        gridBarrier();

        // D: controller split-K (128)
        for (int it = blockIdx.x; it < 128; it += NBLK) {
            int c = it >> 5, rest = it & 31, tm = rest >> 3, tn = rest & 7;
            gemmD_tile(c, tm * 64, tn * 64, x + (size_t)t * Ii, Wx, Wr, shbuf);
        }
        gridBarrier();

        // D2: h = tanh(sum hpart + bh)
        for (int i = gtid; i < BH; i += gstride)
            g_h[i] = tanh_f(g_hpart[i] + g_hpart[i + BH] + g_hpart[i + 2 * BH]
                            + g_hpart[i + 3 * BH] + bh[i & 511]);
        gridBarrier();

        // E: pw(36) + pr(36) + ea-next(64) = 136 items, single round
        for (int it = blockIdx.x; it < 136; it += NBLK) {
            if (it < 36) {
                int tm = it / 9, tn = it % 9;
                gemm64_nn(g_h, Hh, Whw, Mm + 6, bhw, g_pw, Mm + 6,
                          tm * 64, tn * 64, Mm + 6, Hh, 3, shbuf);
            } else if (it < 72) {
                int i2 = it - 36, tm = i2 / 9, tn = i2 % 9;
                gemm64_nn(g_h, Hh, Whr, Mm + 6, bhr, g_pr, Mm + 6,
                          tm * 64, tn * 64, Mm + 6, Hh, 3, shbuf);
            } else {
                int i2 = it - 72, tm = i2 >> 4, tn = i2 & 15;
                gemm64_nn(g_h, Hh, Wea, 2 * Mm, bea, g_ea, 2 * Mm,
                          tm * 64, tn * 64, 2 * Mm, Hh, 4, shbuf);
            }
        }
        gridBarrier();

        // F: simw(64) simr(64) + head scalars(16) = 144
        for (int it = blockIdx.x; it < 144; it += NBLK) {
            if (it < 64) {
                int tm = it >> 4, tn = it & 15;
                gemm64_nt(g_pw, Mm + 6, g_mem, Mm, g_simw, Nn,
                          tm * 64, tn * 64, Mm, shbuf);
            } else if (it < 128) {
                int i2 = it - 64, tm = i2 >> 4, tn = i2 & 15;
                gemm64_nt(g_pr, Mm + 6, g_mem, Mm, g_simr, Nn,
                          tm * 64, tn * 64, Mm, shbuf);
            } else scalars_item(it - 128);
        }
        gridBarrier();

        // G: address tails (512 rows)
        for (int it = blockIdx.x; it < 512; it += NBLK)
            tail_item(it, shbuf);
        gridBarrier();
    }

    // final out for t = 127 (h still holds h_127)
    for (int it = blockIdx.x; it < 32; it += NBLK) {
        gemm64_nn(g_h, Hh, Wo, Oo, bo, out + (size_t)(Tt - 1) * Oo, Tt * Oo,
                  (it >> 3) * 64, (it & 7) * 64, Oo, Hh, 2, shbuf);
    }
}

// ---------------- host --------------------------------------------------------
extern "C" void kernel_launch(void* const* d_in, const int* in_sizes, int n_in,
                              void* d_out, int out_size)
{
    const float* x    = (const float*)d_in[0];
    const float* mem0 = (const float*)d_in[1];
    const float* wr0  = (const float*)d_in[2];
    const float* ww0  = (const float*)d_in[3];
    const float* h0   = (const float*)d_in[4];
    const float* Wx   = (const float*)d_in[5];
    const float* Wr   = (const float*)d_in[6];
    const float* bh   = (const float*)d_in[7];
    const float* Whr  = (const float*)d_in[8];
    const float* bhr  = (const float*)d_in[9];
    const float* Whw  = (const float*)d_in[10];
    const float* bhw  = (const float*)d_in[11];
    const float* Wea  = (const float*)d_in[12];
    const float* bea  = (const float*)d_in[13];
    const float* Wo   = (const float*)d_in[14];
    const float* bo   = (const float*)d_in[15];
    float* out = (float*)d_out;

    ntm_persistent<<<NBLK, NTHR>>>(x, mem0, wr0, ww0, h0, Wx, Wr, bh,
                                   Whr, bhr, Whw, bhw, Wea, bea, Wo, bo, out);
}

// round 6
// speedup vs baseline: 3.0760x; 3.0760x over previous
#include <cuda_runtime.h>
#include <math.h>

// NTM shapes
#define Bb 256
#define Tt 128
#define Ii 512
#define Hh 512
#define Nn 1024
#define Mm 512
#define Oo 512
#define NBLK 148
#define NTHR 256
#define BH (Bb * Hh)
#define BM (Bb * Mm)

typedef unsigned long long ull;

// ---------------- persistent state / scratch (device globals) ---------------
__device__ float g_mem[Nn * Mm];
__device__ float g_wr[Bb * Nn];
__device__ float g_ww[Bb * Nn];
__device__ float g_h[Bb * Hh];
__device__ float g_ea[Bb * 2 * Mm];
__device__ float g_rpart[4 * Bb * Mm];
__device__ float g_hpart[4 * Bb * Hh];
__device__ float g_pw[Bb * (Mm + 6)];
__device__ float g_pr[Bb * (Mm + 6)];
__device__ float g_scw[Bb * 8];
__device__ float g_scr[Bb * 8];
__device__ float g_simw[Bb * Nn];
__device__ float g_simr[Bb * Nn];
__device__ float g_invmem[Nn];
__device__ unsigned g_bar_count;
__device__ unsigned g_bar_gen;

// ---------------- grid barrier ----------------------------------------------
static __device__ __forceinline__ void gridBarrier() {
    __syncthreads();
    __threadfence();
    if (threadIdx.x == 0) {
        unsigned gen = *(volatile unsigned*)&g_bar_gen;
        unsigned prev = atomicAdd(&g_bar_count, 1u);
        if (prev == NBLK - 1) {
            g_bar_count = 0;
            __threadfence();
            *(volatile unsigned*)&g_bar_gen = gen + 1;
        } else {
            while (*(volatile unsigned*)&g_bar_gen == gen) { __nanosleep(64); }
        }
    }
    __syncthreads();
}

// ---------------- packed f32x2 helpers ---------------------------------------
static __device__ __forceinline__ void fmax2(ull &d, ull a, ull b) {
    asm("fma.rn.f32x2 %0, %1, %2, %3;" : "=l"(d) : "l"(a), "l"(b), "l"(d));
}
static __device__ __forceinline__ ull bcast2(float x) {
    ull r;
    asm("mov.b64 %0, {%1, %1};" : "=l"(r) : "f"(x));
    return r;
}
static __device__ __forceinline__ float2 unpack2(ull v) {
    float2 f;
    asm("mov.b64 {%0, %1}, %2;" : "=f"(f.x), "=f"(f.y) : "l"(v));
    return f;
}

// ---------------- math helpers ----------------------------------------------
static __device__ __forceinline__ float sigm(float x) { return 1.f / (1.f + __expf(-x)); }
static __device__ __forceinline__ float tanh_f(float x) {
    float t = __expf(-2.f * fabsf(x));
    float r = (1.f - t) / (1.f + t);
    return copysignf(r, x);
}
static __device__ __forceinline__ float softplus_(float x) {
    return fmaxf(x, 0.f) + log1pf(__expf(-fabsf(x)));
}
static __device__ __forceinline__ float warpReduceSum(float v) {
    #pragma unroll
    for (int o = 16; o > 0; o >>= 1) v += __shfl_xor_sync(0xffffffffu, v, o);
    return v;
}
static __device__ __forceinline__ float warpReduceMax(float v) {
    #pragma unroll
    for (int o = 16; o > 0; o >>= 1) v = fmaxf(v, __shfl_xor_sync(0xffffffffu, v, o));
    return v;
}
static __device__ __forceinline__ float blockReduceSum256(float v) {
    __shared__ float sh[8];
    int lane = threadIdx.x & 31, wid = threadIdx.x >> 5;
    v = warpReduceSum(v);
    if (lane == 0) sh[wid] = v;
    __syncthreads();
    if (wid == 0) {
        float t = (lane < 8) ? sh[lane] : 0.f;
        t = warpReduceSum(t);
        if (lane == 0) sh[0] = t;
    }
    __syncthreads();
    float r = sh[0];
    __syncthreads();
    return r;
}
static __device__ __forceinline__ float blockReduceMax256(float v) {
    __shared__ float sh[8];
    int lane = threadIdx.x & 31, wid = threadIdx.x >> 5;
    v = warpReduceMax(v);
    if (lane == 0) sh[wid] = v;
    __syncthreads();
    if (wid == 0) {
        float t = (lane < 8) ? sh[lane] : -3.4e38f;
        t = warpReduceMax(t);
        if (lane == 0) sh[0] = t;
    }
    __syncthreads();
    float r = sh[0];
    __syncthreads();
    return r;
}

// inner 4x4 (as 4 rows x 2 col-pairs) f32x2 step
#define FMA16X2(acc, a4, wv)                                           \
    {                                                                  \
        ull a0_ = bcast2(a4.x), a1_ = bcast2(a4.y);                    \
        ull a2_ = bcast2(a4.z), a3_ = bcast2(a4.w);                    \
        fmax2(acc[0][0], a0_, wv.x); fmax2(acc[0][1], a0_, wv.y);      \
        fmax2(acc[1][0], a1_, wv.x); fmax2(acc[1][1], a1_, wv.y);      \
        fmax2(acc[2][0], a2_, wv.x); fmax2(acc[2][1], a2_, wv.y);      \
        fmax2(acc[3][0], a3_, wv.x); fmax2(acc[3][1], a3_, wv.y);      \
    }

// ---------------- 64x64 NN GEMM tile, double-buffered, f32x2 -----------------
// C = act(A@W + bias).  act: 0 none, 2 sigmoid, 3 tanh col<512, 4 sig|tanh.
static __device__ __forceinline__ void gemm64_nn(
    const float* __restrict__ A, int lda,
    const float* __restrict__ W, int ldw,
    const float* __restrict__ bias,
    float* __restrict__ C, int ldc,
    int bm, int bn, int Nc, int K, int act, float* shb)
{
    float (*As)[16][68] = (float(*)[16][68])shb;
    float (*Ws)[16][64] = (float(*)[16][64])(shb + 2 * 16 * 68);
    const int tid = threadIdx.x, tx = tid & 15, ty = tid >> 4;
    const int am = tid >> 4, ak = tid & 15;
    const int wk = tid >> 6, wn = tid & 63;
    const float* Aptr = A + (size_t)(bm + am) * lda + ak;
    const float* Wptr = W + (size_t)wk * ldw + bn + wn;
    const bool wok = (bn + wn) < Nc;

    ull acc[4][2] = {};
    float ra[4], rw[4];
    #pragma unroll
    for (int i = 0; i < 4; i++) {
        ra[i] = Aptr[i * 16 * lda];
        rw[i] = wok ? Wptr[(size_t)(i * 4) * ldw] : 0.f;
    }
    #pragma unroll
    for (int i = 0; i < 4; i++) {
        As[0][ak][am + 16 * i] = ra[i];
        Ws[0][wk + 4 * i][wn] = rw[i];
    }
    __syncthreads();
    int buf = 0;
    for (int k0 = 0; k0 < K; k0 += 16) {
        if (k0 + 16 < K) {
            const float* Ap = Aptr + (k0 + 16);
            const float* Wp = Wptr + (size_t)(k0 + 16) * ldw;
            #pragma unroll
            for (int i = 0; i < 4; i++) {
                ra[i] = Ap[i * 16 * lda];
                rw[i] = wok ? Wp[(size_t)(i * 4) * ldw] : 0.f;
            }
        }
        #pragma unroll
        for (int kk = 0; kk < 16; kk++) {
            float4 a4 = *(const float4*)&As[buf][kk][ty * 4];
            ulonglong2 w2 = *(const ulonglong2*)&Ws[buf][kk][tx * 4];
            FMA16X2(acc, a4, w2);
        }
        if (k0 + 16 < K) {
            __syncthreads();
            #pragma unroll
            for (int i = 0; i < 4; i++) {
                As[buf ^ 1][ak][am + 16 * i] = ra[i];
                Ws[buf ^ 1][wk + 4 * i][wn] = rw[i];
            }
            __syncthreads();
            buf ^= 1;
        }
    }
    __syncthreads();
    #pragma unroll
    for (int i = 0; i < 4; i++) {
        int row = bm + ty * 4 + i;
        float2 v01 = unpack2(acc[i][0]);
        float2 v23 = unpack2(acc[i][1]);
        float vals[4] = {v01.x, v01.y, v23.x, v23.y};
        #pragma unroll
        for (int j = 0; j < 4; j++) {
            int col = bn + tx * 4 + j;
            if (col >= Nc) continue;
            float v = vals[j];
            if (bias) v += bias[col];
            if (act == 2) v = sigm(v);
            else if (act == 3) { if (col < 512) v = tanh_f(v); }
            else if (act == 4) { v = (col < 512) ? sigm(v) : tanh_f(v); }
            C[(size_t)row * ldc + col] = v;
        }
    }
}

// ---------------- 64x64 NT GEMM tile, double-buffered, f32x2 -----------------
static __device__ __forceinline__ void gemm64_nt(
    const float* __restrict__ A, int lda,
    const float* __restrict__ Bm, int ldb,
    float* __restrict__ C, int ldc,
    int bm, int bn, int K, float* shb)
{
    float (*As)[16][68] = (float(*)[16][68])shb;
    float (*Bs)[16][68] = (float(*)[16][68])(shb + 2 * 16 * 68);
    const int tid = threadIdx.x, tx = tid & 15, ty = tid >> 4;
    const int am = tid >> 4, ak = tid & 15;
    const float* Aptr = A + (size_t)(bm + am) * lda + ak;
    const float* Bptr = Bm + (size_t)(bn + am) * ldb + ak;

    ull acc[4][2] = {};
    float ra[4], rb[4];
    #pragma unroll
    for (int i = 0; i < 4; i++) {
        ra[i] = Aptr[i * 16 * lda];
        rb[i] = Bptr[i * 16 * ldb];
    }
    #pragma unroll
    for (int i = 0; i < 4; i++) {
        As[0][ak][am + 16 * i] = ra[i];
        Bs[0][ak][am + 16 * i] = rb[i];
    }
    __syncthreads();
    int buf = 0;
    for (int k0 = 0; k0 < K; k0 += 16) {
        if (k0 + 16 < K) {
            const float* Ap = Aptr + (k0 + 16);
            const float* Bp = Bptr + (k0 + 16);
            #pragma unroll
            for (int i = 0; i < 4; i++) {
                ra[i] = Ap[i * 16 * lda];
                rb[i] = Bp[i * 16 * ldb];
            }
        }
        #pragma unroll
        for (int kk = 0; kk < 16; kk++) {
            float4 a4 = *(const float4*)&As[buf][kk][ty * 4];
            ulonglong2 w2 = *(const ulonglong2*)&Bs[buf][kk][tx * 4];
            FMA16X2(acc, a4, w2);
        }
        if (k0 + 16 < K) {
            __syncthreads();
            #pragma unroll
            for (int i = 0; i < 4; i++) {
                As[buf ^ 1][ak][am + 16 * i] = ra[i];
                Bs[buf ^ 1][ak][am + 16 * i] = rb[i];
            }
            __syncthreads();
            buf ^= 1;
        }
    }
    __syncthreads();
    #pragma unroll
    for (int i = 0; i < 4; i++) {
        int row = bm + ty * 4 + i;
        float2 v01 = unpack2(acc[i][0]);
        float2 v23 = unpack2(acc[i][1]);
        C[(size_t)row * ldc + (bn + tx * 4 + 0)] = v01.x;
        C[(size_t)row * ldc + (bn + tx * 4 + 1)] = v01.y;
        C[(size_t)row * ldc + (bn + tx * 4 + 2)] = v23.x;
        C[(size_t)row * ldc + (bn + tx * 4 + 3)] = v23.y;
    }
}

// ---------------- mem update tile, double-buffered, f32x2 --------------------
static __device__ __forceinline__ void memupd_tile(int tn, int tm, float* shb)
{
    float (*Wws)[16][68] = (float(*)[16][68])shb;
    float (*Es)[16][68]  = (float(*)[16][68])(shb + 2 * 16 * 68);
    float (*Aas)[16][68] = (float(*)[16][68])(shb + 4 * 16 * 68);
    const int bnrow = tn * 64, bmcol = tm * 64;
    const int tid = threadIdx.x, tx = tid & 15, ty = tid >> 4;
    const int lk = tid >> 6, lc = tid & 63;
    const float* wp = g_ww + (size_t)lk * Nn + bnrow + lc;
    const float* ep = g_ea + (size_t)lk * (2 * Mm) + bmcol + lc;
    const float* ap = ep + Mm;

    ull acce[4][2] = {};
    ull acca[4][2] = {};
    float rw[4], re[4], rr[4];
    #pragma unroll
    for (int i = 0; i < 4; i++) {
        rw[i] = wp[(size_t)(4 * i) * Nn];
        re[i] = ep[(size_t)(4 * i) * (2 * Mm)];
        rr[i] = ap[(size_t)(4 * i) * (2 * Mm)];
    }
    #pragma unroll
    for (int i = 0; i < 4; i++) {
        Wws[0][lk + 4 * i][lc] = rw[i];
        Es[0][lk + 4 * i][lc] = re[i];
        Aas[0][lk + 4 * i][lc] = rr[i];
    }
    __syncthreads();
    int buf = 0;
    for (int b0 = 0; b0 < Bb; b0 += 16) {
        if (b0 + 16 < Bb) {
            const float* wp2 = wp + (size_t)(b0 + 16) * Nn;
            const float* ep2 = ep + (size_t)(b0 + 16) * (2 * Mm);
            const float* ap2 = ap + (size_t)(b0 + 16) * (2 * Mm);
            #pragma unroll
            for (int i = 0; i < 4; i++) {
                rw[i] = wp2[(size_t)(4 * i) * Nn];
                re[i] = ep2[(size_t)(4 * i) * (2 * Mm)];
                rr[i] = ap2[(size_t)(4 * i) * (2 * Mm)];
            }
        }
        #pragma unroll
        for (int kk = 0; kk < 16; kk++) {
            float4 w4 = *(const float4*)&Wws[buf][kk][ty * 4];
            ulonglong2 e2 = *(const ulonglong2*)&Es[buf][kk][tx * 4];
            ulonglong2 a2 = *(const ulonglong2*)&Aas[buf][kk][tx * 4];
            ull b0_ = bcast2(w4.x), b1_ = bcast2(w4.y);
            ull b2_ = bcast2(w4.z), b3_ = bcast2(w4.w);
            fmax2(acce[0][0], b0_, e2.x); fmax2(acce[0][1], b0_, e2.y);
            fmax2(acce[1][0], b1_, e2.x); fmax2(acce[1][1], b1_, e2.y);
            fmax2(acce[2][0], b2_, e2.x); fmax2(acce[2][1], b2_, e2.y);
            fmax2(acce[3][0], b3_, e2.x); fmax2(acce[3][1], b3_, e2.y);
            fmax2(acca[0][0], b0_, a2.x); fmax2(acca[0][1], b0_, a2.y);
            fmax2(acca[1][0], b1_, a2.x); fmax2(acca[1][1], b1_, a2.y);
            fmax2(acca[2][0], b2_, a2.x); fmax2(acca[2][1], b2_, a2.y);
            fmax2(acca[3][0], b3_, a2.x); fmax2(acca[3][1], b3_, a2.y);
        }
        if (b0 + 16 < Bb) {
            __syncthreads();
            #pragma unroll
            for (int i = 0; i < 4; i++) {
                Wws[buf ^ 1][lk + 4 * i][lc] = rw[i];
                Es[buf ^ 1][lk + 4 * i][lc] = re[i];
                Aas[buf ^ 1][lk + 4 * i][lc] = rr[i];
            }
            __syncthreads();
            buf ^= 1;
        }
    }
    __syncthreads();
    const float invB = 1.f / (float)Bb;
    #pragma unroll
    for (int i = 0; i < 4; i++) {
        int n = bnrow + ty * 4 + i;
        float2 e01 = unpack2(acce[i][0]);
        float2 e23 = unpack2(acce[i][1]);
        float2 a01 = unpack2(acca[i][0]);
        float2 a23 = unpack2(acca[i][1]);
        float ev[4] = {e01.x, e01.y, e23.x, e23.y};
        float av[4] = {a01.x, a01.y, a23.x, a23.y};
        #pragma unroll
        for (int j = 0; j < 4; j++) {
            int m = bmcol + tx * 4 + j;
            float old = g_mem[(size_t)n * Mm + m];
            g_mem[(size_t)n * Mm + m] = old * (1.f - ev[j] * invB) + av[j] * invB;
        }
    }
}

// ---------------- controller split-K tile, f32x2 ----------------------------
// chunk c: 0,1 -> x halves; 2,3 -> r (= sum of 4 rpart) halves. K=256 each.
static __device__ __forceinline__ void gemmD_tile(
    int c, int bm, int bn, const float* __restrict__ xb,
    const float* __restrict__ Wx, const float* __restrict__ Wr, float* shb)
{
    float (*As)[16][68] = (float(*)[16][68])shb;
    float (*Ws)[16][64] = (float(*)[16][64])(shb + 2 * 16 * 68);
    const int tid = threadIdx.x, tx = tid & 15, ty = tid >> 4;
    const int am = tid >> 4, ak = tid & 15;
    const int wk = tid >> 6, wn = tid & 63;
    const float* Wptr = ((c < 2) ? (Wx + (size_t)c * 256 * Hh)
                                 : (Wr + (size_t)(c - 2) * 256 * Hh))
                        + (size_t)wk * Hh + bn + wn;
    const float* Ax = xb + (size_t)(bm + am) * (Tt * Ii) + c * 256 + ak;
    const float* Ar = g_rpart + (size_t)(bm + am) * Mm + (c - 2) * 256 + ak;

    ull acc[4][2] = {};
    float ra[4], rw[4];
    #pragma unroll
    for (int i = 0; i < 4; i++) {
        if (c < 2) ra[i] = Ax[(size_t)(i * 16) * (Tt * Ii)];
        else {
            const float* p = Ar + (size_t)(i * 16) * Mm;
            ra[i] = p[0] + p[BM] + p[2 * BM] + p[3 * BM];
        }
        rw[i] = Wptr[(size_t)(i * 4) * Hh];
    }
    #pragma unroll
    for (int i = 0; i < 4; i++) {
        As[0][ak][am + 16 * i] = ra[i];
        Ws[0][wk + 4 * i][wn] = rw[i];
    }
    __syncthreads();
    int buf = 0;
    for (int k0 = 0; k0 < 256; k0 += 16) {
        if (k0 + 16 < 256) {
            #pragma unroll
            for (int i = 0; i < 4; i++) {
                if (c < 2) ra[i] = Ax[(size_t)(i * 16) * (Tt * Ii) + k0 + 16];
                else {
                    const float* p = Ar + (size_t)(i * 16) * Mm + k0 + 16;
                    ra[i] = p[0] + p[BM] + p[2 * BM] + p[3 * BM];
                }
                rw[i] = Wptr[(size_t)(k0 + 16 + i * 4) * Hh];
            }
        }
        #pragma unroll
        for (int kk = 0; kk < 16; kk++) {
            float4 a4 = *(const float4*)&As[buf][kk][ty * 4];
            ulonglong2 w2 = *(const ulonglong2*)&Ws[buf][kk][tx * 4];
            FMA16X2(acc, a4, w2);
        }
        if (k0 + 16 < 256) {
            __syncthreads();
            #pragma unroll
            for (int i = 0; i < 4; i++) {
                As[buf ^ 1][ak][am + 16 * i] = ra[i];
                Ws[buf ^ 1][wk + 4 * i][wn] = rw[i];
            }
            __syncthreads();
            buf ^= 1;
        }
    }
    __syncthreads();
    float* C = g_hpart + (size_t)c * BH;
    #pragma unroll
    for (int i = 0; i < 4; i++) {
        int row = bm + ty * 4 + i;
        float2 v01 = unpack2(acc[i][0]);
        float2 v23 = unpack2(acc[i][1]);
        C[(size_t)row * Hh + (bn + tx * 4 + 0)] = v01.x;
        C[(size_t)row * Hh + (bn + tx * 4 + 1)] = v01.y;
        C[(size_t)row * Hh + (bn + tx * 4 + 2)] = v23.x;
        C[(size_t)row * Hh + (bn + tx * 4 + 3)] = v23.y;
    }
}

// ---------------- small row-wise items ---------------------------------------
static __device__ __noinline__ void invnorm_item(int item)
{
    int w = threadIdx.x >> 5, lane = threadIdx.x & 31;
    for (int rr = w; rr < 128; rr += 8) {
        int n = item * 128 + rr;
        float s = 0.f;
        for (int c = lane; c < Mm; c += 32) {
            float v = g_mem[(size_t)n * Mm + c];
            s += v * v;
        }
        s = warpReduceSum(s);
        if (lane == 0) g_invmem[n] = 1.f / (sqrtf(s) + 1e-8f);
    }
}

static __device__ __noinline__ void scalars_item(int i)
{
    int head = i >> 3, rb = i & 7;
    const float* p = head ? g_pr : g_pw;
    float* sc = head ? g_scr : g_scw;
    int w = threadIdx.x >> 5, lane = threadIdx.x & 31;
    for (int rr = w; rr < 32; rr += 8) {
        int b = rb * 32 + rr;
        const float* row = p + (size_t)b * (Mm + 6);
        float s = 0.f;
        for (int c = lane; c < Mm; c += 32) {
            float v = row[c];
            s += v * v;
        }
        s = warpReduceSum(s);
        if (lane == 0) {
            sc[b * 8 + 0] = softplus_(row[Mm + 0]);
            sc[b * 8 + 1] = sigm(row[Mm + 1]);
            float s0 = row[Mm + 2], s1 = row[Mm + 3], s2 = row[Mm + 4];
            float mx = fmaxf(s0, fmaxf(s1, s2));
            float e0 = __expf(s0 - mx), e1 = __expf(s1 - mx), e2 = __expf(s2 - mx);
            float inv = 1.f / (e0 + e1 + e2);
            sc[b * 8 + 2] = e0 * inv;
            sc[b * 8 + 3] = e1 * inv;
            sc[b * 8 + 4] = e2 * inv;
            sc[b * 8 + 5] = 1.f + softplus_(row[Mm + 5]);
            sc[b * 8 + 6] = 1.f / (sqrtf(s) + 1e-8f);
        }
    }
}

// -------- fused address tail: softmax -> interpolate -> shift -> sharpen -----
static __device__ __noinline__ void tail_item(int it, float* shb)
{
    float* wg = shb;                  // 1024 floats
    int b = it & 255, head = it >> 8;
    const float* sim = head ? g_simr : g_simw;
    float* wv = head ? g_wr : g_ww;
    const float* sc = head ? g_scr : g_scw;
    int tid = threadIdx.x;
    float beta = sc[b * 8 + 0], g = sc[b * 8 + 1];
    float s0 = sc[b * 8 + 2], s1 = sc[b * 8 + 3], s2 = sc[b * 8 + 4];
    float gamma = sc[b * 8 + 5], invk = sc[b * 8 + 6];
    float scale = beta * invk;

    float v[4];
    float mx = -3.4e38f;
    #pragma unroll
    for (int i = 0; i < 4; i++) {
        int n = tid + i * 256;
        float t = sim[(size_t)b * Nn + n] * scale * g_invmem[n];
        v[i] = t;
        mx = fmaxf(mx, t);
    }
    mx = blockReduceMax256(mx);
    float s = 0.f;
    #pragma unroll
    for (int i = 0; i < 4; i++) { v[i] = __expf(v[i] - mx); s += v[i]; }
    s = blockReduceSum256(s);
    float invs = 1.f / s;
    #pragma unroll
    for (int i = 0; i < 4; i++) {
        int n = tid + i * 256;
        wg[n] = g * (v[i] * invs) + (1.f - g) * wv[(size_t)b * Nn + n];
    }
    __syncthreads();
    float wp[4];
    float local = 0.f;
    #pragma unroll
    for (int i = 0; i < 4; i++) {
        int n = tid + i * 256;
        float wt = s0 * wg[(n + 1) & (Nn - 1)] + s1 * wg[n] + s2 * wg[(n - 1) & (Nn - 1)];
        float pv = __powf(wt, gamma);
        wp[i] = pv;
        local += pv;
    }
    local = blockReduceSum256(local);
    float invt = 1.f / (local + 1e-8f);
    #pragma unroll
    for (int i = 0; i < 4; i++) {
        int n = tid + i * 256;
        wv[(size_t)b * Nn + n] = wp[i] * invt;
    }
    __syncthreads();
}

// ---------------- the persistent kernel --------------------------------------
__global__ void __launch_bounds__(NTHR, 1) ntm_persistent(
    const float* __restrict__ x,
    const float* __restrict__ mem0, const float* __restrict__ wr0,
    const float* __restrict__ ww0,  const float* __restrict__ h0,
    const float* __restrict__ Wx,   const float* __restrict__ Wr,
    const float* __restrict__ bh,
    const float* __restrict__ Whr,  const float* __restrict__ bhr,
    const float* __restrict__ Whw,  const float* __restrict__ bhw,
    const float* __restrict__ Wea,  const float* __restrict__ bea,
    const float* __restrict__ Wo,   const float* __restrict__ bo,
    float* __restrict__ out)
{
    __shared__ __align__(16) float shbuf[6 * 16 * 68];   // 26.1 KB
    const int tid = threadIdx.x;
    const int gtid = blockIdx.x * NTHR + tid;
    const int gstride = NBLK * NTHR;

    // P0: init carried state
    for (int i = gtid; i < Nn * Mm; i += gstride) g_mem[i] = mem0[i];
    for (int i = gtid; i < Bb * Nn; i += gstride) { g_wr[i] = wr0[i]; g_ww[i] = ww0[i]; }
    for (int i = gtid; i < Bb * Hh; i += gstride) g_h[i] = h0[i];
    gridBarrier();

    // P1: ea from h0 (64 tiles)
    for (int it = blockIdx.x; it < 64; it += NBLK) {
        int tm = it >> 4, tn = it & 15;
        gemm64_nn(g_h, Hh, Wea, 2 * Mm, bea, g_ea, 2 * Mm,
                  tm * 64, tn * 64, 2 * Mm, Hh, 4, shbuf);
    }
    gridBarrier();

    for (int t = 0; t < Tt; t++) {
        // B: memupd (128) + out_{t-1} tiles 0..19  => exactly 148 items
        for (int it = blockIdx.x; it < 148; it += NBLK) {
            if (it < 128) memupd_tile(it >> 3, it & 7, shbuf);
            else if (t > 0) {
                int o = it - 128;                         // 0..19
                gemm64_nn(g_h, Hh, Wo, Oo, bo, out + (size_t)(t - 1) * Oo, Tt * Oo,
                          (o >> 3) * 64, (o & 7) * 64, Oo, Hh, 2, shbuf);
            }
        }
        gridBarrier();

        // C: r split-K (128) + invnorm (8) + out_{t-1} tiles 20..31 => 148
        for (int it = blockIdx.x; it < 148; it += NBLK) {
            if (it < 128) {
                int c = it >> 5, rest = it & 31, tm = rest >> 3, tn = rest & 7;
                gemm64_nn(g_wr + c * 256, Nn, g_mem + (size_t)c * 256 * Mm, Mm, nullptr,
                          g_rpart + (size_t)c * BM, Mm, tm * 64, tn * 64, Mm, 256, 0, shbuf);
            } else if (it < 136) invnorm_item(it - 128);
            else if (t > 0) {
                int o = it - 136 + 20;                    // 20..31
                gemm64_nn(g_h, Hh, Wo, Oo, bo, out + (size_t)(t - 1) * Oo, Tt * Oo,
                          (o >> 3) * 64, (o & 7) * 64, Oo, Hh, 2, shbuf);
            }
        }
        gridBarrier();

        // D: controller split-K (128)
        for (int it = blockIdx.x; it < 128; it += NBLK) {
            int c = it >> 5, rest = it & 31, tm = rest >> 3, tn = rest & 7;
            gemmD_tile(c, tm * 64, tn * 64, x + (size_t)t * Ii, Wx, Wr, shbuf);
        }
        gridBarrier();

        // D2: h = tanh(sum hpart + bh)
        for (int i = gtid; i < BH; i += gstride)
            g_h[i] = tanh_f(g_hpart[i] + g_hpart[i + BH] + g_hpart[i + 2 * BH]
                            + g_hpart[i + 3 * BH] + bh[i & 511]);
        gridBarrier();

        // E: pw(36) + pr(36) + ea-next(64) = 136 items, single round
        for (int it = blockIdx.x; it < 136; it += NBLK) {
            if (it < 36) {
                int tm = it / 9, tn = it % 9;
                gemm64_nn(g_h, Hh, Whw, Mm + 6, bhw, g_pw, Mm + 6,
                          tm * 64, tn * 64, Mm + 6, Hh, 3, shbuf);
            } else if (it < 72) {
                int i2 = it - 36, tm = i2 / 9, tn = i2 % 9;
                gemm64_nn(g_h, Hh, Whr, Mm + 6, bhr, g_pr, Mm + 6,
                          tm * 64, tn * 64, Mm + 6, Hh, 3, shbuf);
            } else {
                int i2 = it - 72, tm = i2 >> 4, tn = i2 & 15;
                gemm64_nn(g_h, Hh, Wea, 2 * Mm, bea, g_ea, 2 * Mm,
                          tm * 64, tn * 64, 2 * Mm, Hh, 4, shbuf);
            }
        }
        gridBarrier();

        // F: simw(64) simr(64) + head scalars(16) = 144
        for (int it = blockIdx.x; it < 144; it += NBLK) {
            if (it < 64) {
                int tm = it >> 4, tn = it & 15;
                gemm64_nt(g_pw, Mm + 6, g_mem, Mm, g_simw, Nn,
                          tm * 64, tn * 64, Mm, shbuf);
            } else if (it < 128) {
                int i2 = it - 64, tm = i2 >> 4, tn = i2 & 15;
                gemm64_nt(g_pr, Mm + 6, g_mem, Mm, g_simr, Nn,
                          tm * 64, tn * 64, Mm, shbuf);
            } else scalars_item(it - 128);
        }
        gridBarrier();

        // G: address tails (512 rows)
        for (int it = blockIdx.x; it < 512; it += NBLK)
            tail_item(it, shbuf);
        gridBarrier();
    }

    // final out for t = 127 (h still holds h_127)
    for (int it = blockIdx.x; it < 32; it += NBLK) {
        gemm64_nn(g_h, Hh, Wo, Oo, bo, out + (size_t)(Tt - 1) * Oo, Tt * Oo,
                  (it >> 3) * 64, (it & 7) * 64, Oo, Hh, 2, shbuf);
    }
}

// ---------------- host --------------------------------------------------------
extern "C" void kernel_launch(void* const* d_in, const int* in_sizes, int n_in,
                              void* d_out, int out_size)
{
    const float* x    = (const float*)d_in[0];
    const float* mem0 = (const float*)d_in[1];
    const float* wr0  = (const float*)d_in[2];
    const float* ww0  = (const float*)d_in[3];
    const float* h0   = (const float*)d_in[4];
    const float* Wx   = (const float*)d_in[5];
    const float* Wr   = (const float*)d_in[6];
    const float* bh   = (const float*)d_in[7];
    const float* Whr  = (const float*)d_in[8];
    const float* bhr  = (const float*)d_in[9];
    const float* Whw  = (const float*)d_in[10];
    const float* bhw  = (const float*)d_in[11];
    const float* Wea  = (const float*)d_in[12];
    const float* bea  = (const float*)d_in[13];
    const float* Wo   = (const float*)d_in[14];
    const float* bo   = (const float*)d_in[15];
    float* out = (float*)d_out;

    ntm_persistent<<<NBLK, NTHR>>>(x, mem0, wr0, ww0, h0, Wx, Wr, bh,
                                   Whr, bhr, Whw, bhw, Wea, bea, Wo, bo, out);
}